// round 1
// baseline (speedup 1.0000x reference)
#include <cuda_runtime.h>
#include <math.h>

// Problem constants (fixed shapes)
#define T_STEPS 2048
#define BATCH   256
#define HID     256
#define OUT_DIM 16

// Scratch (device globals: allocation-free kernel_launch)
__device__ float g_xp[134217728];      // [T][B][H] = 2048*256*256 floats = 512 MB
__device__ float g_hfinal[BATCH * HID];

// ---------------------------------------------------------------------------
// f32x2 packed-FMA helpers (sm_103a packed fp32 pipe; 2x FFMA rate)
// ---------------------------------------------------------------------------
__device__ __forceinline__ unsigned long long f32x2_dup(float w) {
    unsigned long long r;
    unsigned int u = __float_as_uint(w);
    asm("mov.b64 %0, {%1, %1};" : "=l"(r) : "r"(u));
    return r;
}
__device__ __forceinline__ unsigned long long f32x2_pack(float x, float y) {
    unsigned long long r;
    asm("mov.b64 %0, {%1, %2};" : "=l"(r) : "r"(__float_as_uint(x)), "r"(__float_as_uint(y)));
    return r;
}
__device__ __forceinline__ void ffma2(unsigned long long& acc,
                                      unsigned long long a, unsigned long long b) {
    asm("fma.rn.f32x2 %0, %1, %2, %0;" : "+l"(acc) : "l"(a), "l"(b));
}

// ---------------------------------------------------------------------------
// Kernel 1: xp[t][b][h] = sum_i x[b][t][i] * W_ih[i][h] + b_h[h]
// Classic 128x128x8 SGEMM, 256 threads, 8x8 microtile.
// A row r = b*2048 + t (x's natural order); C row scattered to (t,b).
// ---------------------------------------------------------------------------
#define BM 128
#define BN 128
#define BK 8

__global__ __launch_bounds__(256)
void gemm_xp_kernel(const float* __restrict__ x,
                    const float* __restrict__ Wih,
                    const float* __restrict__ bh) {
    __shared__ float As[BK][BM];   // A tile, k-major (transposed on store)
    __shared__ float Bs[BK][BN];

    const int tid = threadIdx.x;
    const int tx = tid & 15;       // 0..15 (n direction)
    const int ty = tid >> 4;       // 0..15 (m direction)

    const size_t r0 = (size_t)blockIdx.x * BM;
    const int    n0 = blockIdx.y * BN;

    // A load mapping: 128 rows x 8 k = 1024 floats -> 1 float4/thread
    const int arow = tid >> 1;
    const int akq  = (tid & 1) * 4;
    // B load mapping: 8 k-rows x 128 n
    const int bkr = tid >> 5;
    const int bn  = (tid & 31) * 4;

    float acc[8][8];
#pragma unroll
    for (int i = 0; i < 8; i++)
#pragma unroll
        for (int j = 0; j < 8; j++) acc[i][j] = 0.f;

    for (int kt = 0; kt < 256; kt += BK) {
        float4 av = *(const float4*)&x[(r0 + arow) * 256 + kt + akq];
        float4 bv = *(const float4*)&Wih[(size_t)(kt + bkr) * 256 + n0 + bn];
        __syncthreads();   // previous tile's compute done before overwrite
        As[akq + 0][arow] = av.x;
        As[akq + 1][arow] = av.y;
        As[akq + 2][arow] = av.z;
        As[akq + 3][arow] = av.w;
        *(float4*)&Bs[bkr][bn] = bv;
        __syncthreads();
#pragma unroll
        for (int kk = 0; kk < BK; kk++) {
            float a[8], b[8];
            *(float4*)(a)     = *(const float4*)&As[kk][ty * 8];
            *(float4*)(a + 4) = *(const float4*)&As[kk][ty * 8 + 4];
            *(float4*)(b)     = *(const float4*)&Bs[kk][tx * 8];
            *(float4*)(b + 4) = *(const float4*)&Bs[kk][tx * 8 + 4];
#pragma unroll
            for (int i = 0; i < 8; i++)
#pragma unroll
                for (int j = 0; j < 8; j++)
                    acc[i][j] += a[i] * b[j];
        }
    }

    float bias[8];
    *(float4*)(bias)     = *(const float4*)&bh[n0 + tx * 8];
    *(float4*)(bias + 4) = *(const float4*)&bh[n0 + tx * 8 + 4];

#pragma unroll
    for (int i = 0; i < 8; i++) {
        size_t r = r0 + ty * 8 + i;
        int t = (int)(r & 2047);   // r % T
        int b = (int)(r >> 11);    // r / T
        size_t cbase = ((size_t)t * BATCH + b) * HID + n0 + tx * 8;
        float4 o0, o1;
        o0.x = acc[i][0] + bias[0];  o0.y = acc[i][1] + bias[1];
        o0.z = acc[i][2] + bias[2];  o0.w = acc[i][3] + bias[3];
        o1.x = acc[i][4] + bias[4];  o1.y = acc[i][5] + bias[5];
        o1.z = acc[i][6] + bias[6];  o1.w = acc[i][7] + bias[7];
        *(float4*)&g_xp[cbase]     = o0;
        *(float4*)&g_xp[cbase + 4] = o1;
    }
}

// ---------------------------------------------------------------------------
// Kernel 2: persistent recurrence. 128 CTAs, 2 batches each, 256 threads.
// Thread j owns output column j for both batches.
// W_hh rows [0,216) in smem (k-quad packed for LDS.128),
// rows [216,256) pre-duplicated f32x2 in registers.
// h stored as float2[k] = (h_b0[k], h_b1[k]) -> one broadcast LDS feeds both.
// Dynamic smem: 216*256*4 + 2*256*8 = 221184 + 4096 = 225280 bytes.
// ---------------------------------------------------------------------------
#define KSM 216
#define KQN 54          // KSM/4
#define KRG 40          // 256 - KSM

__global__ __launch_bounds__(256, 1)
void rnn_recurrence_kernel(const float* __restrict__ W_hh) {
    extern __shared__ float smem[];
    float4* Wq    = (float4*)smem;                   // [KQN][256]
    float2* hbufA = (float2*)(smem + KSM * 256);     // [256]
    float2* hbufB = hbufA + 256;                     // [256]

    const int j  = threadIdx.x;
    const int b0 = blockIdx.x * 2;

    // Load W_hh rows [0,216) into k-quad-packed smem (one-time cost)
    for (int idx = j; idx < KSM * 256; idx += 256) {
        int k  = idx >> 8;
        int jj = idx & 255;
        ((float*)&Wq[(k >> 2) * 256 + jj])[k & 3] = W_hh[idx];
    }
    // Rows [216,256): column j duplicated into f32x2 registers
    unsigned long long wreg[KRG];
#pragma unroll
    for (int r = 0; r < KRG; r++)
        wreg[r] = f32x2_dup(W_hh[(KSM + r) * 256 + j]);

    hbufA[j] = make_float2(0.f, 0.f);
    __syncthreads();

    float2* hc = hbufA;
    float2* hn = hbufB;

    const float* xp = g_xp + (size_t)b0 * HID + j;
    float p0 = xp[0];
    float p1 = xp[HID];

    for (int t = 0; t < T_STEPS; t++) {
        unsigned long long acc = f32x2_pack(p0, p1);

        // software-prefetch next step's xp (hidden behind the k-loop)
        int tn = (t + 1 < T_STEPS) ? (t + 1) : t;
        p0 = xp[(size_t)tn * (BATCH * HID)];
        p1 = xp[(size_t)tn * (BATCH * HID) + HID];

        const ulonglong2* hq = (const ulonglong2*)hc;
        const float4* wp = Wq + j;
#pragma unroll 6
        for (int kq = 0; kq < KQN; kq++) {
            float4 w4 = wp[kq * 256];            // W[4kq..4kq+3][j]
            ulonglong2 hA = hq[2 * kq];          // (h2_{4kq}, h2_{4kq+1}) broadcast
            ulonglong2 hB = hq[2 * kq + 1];      // (h2_{4kq+2}, h2_{4kq+3})
            ffma2(acc, hA.x, f32x2_dup(w4.x));
            ffma2(acc, hA.y, f32x2_dup(w4.y));
            ffma2(acc, hB.x, f32x2_dup(w4.z));
            ffma2(acc, hB.y, f32x2_dup(w4.w));
        }
        const unsigned long long* h1 = (const unsigned long long*)(hc + KSM);
#pragma unroll
        for (int r = 0; r < KRG; r++)
            ffma2(acc, h1[r], wreg[r]);

        unsigned int lo, hi;
        asm("mov.b64 {%0, %1}, %2;" : "=r"(lo), "=r"(hi) : "l"(acc));
        float h0v = tanhf(__uint_as_float(lo));
        float h1v = tanhf(__uint_as_float(hi));
        hn[j] = make_float2(h0v, h1v);
        __syncthreads();
        float2* tmp = hc; hc = hn; hn = tmp;
    }

    float2 hf = hc[j];
    g_hfinal[(size_t)b0 * HID + j]       = hf.x;
    g_hfinal[(size_t)(b0 + 1) * HID + j] = hf.y;
}

// ---------------------------------------------------------------------------
// Kernel 3: out[b][o] = h_final[b][:] . fc_w[o][:] + fc_b[o]   (tiny)
// ---------------------------------------------------------------------------
__global__ __launch_bounds__(128)
void rnn_head_kernel(const float* __restrict__ fcw,
                     const float* __restrict__ fcb,
                     float* __restrict__ out) {
    __shared__ float hs[HID];
    __shared__ float part[8][OUT_DIM];
    const int b = blockIdx.x;
    const int tid = threadIdx.x;

    hs[tid]       = g_hfinal[(size_t)b * HID + tid];
    hs[tid + 128] = g_hfinal[(size_t)b * HID + tid + 128];
    __syncthreads();

    const int o   = tid & 15;
    const int seg = tid >> 4;           // 8 segments of 32
    float s = 0.f;
#pragma unroll
    for (int jj = 0; jj < 32; jj++) {
        int j = seg * 32 + jj;
        s += hs[j] * fcw[o * HID + j];
    }
    part[seg][o] = s;
    __syncthreads();
    if (tid < OUT_DIM) {
        float r = fcb[tid];
#pragma unroll
        for (int sg = 0; sg < 8; sg++) r += part[sg][tid];
        out[b * OUT_DIM + tid] = r;
    }
}

// ---------------------------------------------------------------------------
extern "C" void kernel_launch(void* const* d_in, const int* in_sizes, int n_in,
                              void* d_out, int out_size) {
    const float* x   = (const float*)d_in[0];
    const float* Wih = (const float*)d_in[1];
    const float* Whh = (const float*)d_in[2];
    const float* bh  = (const float*)d_in[3];
    const float* fcw = (const float*)d_in[4];
    const float* fcb = (const float*)d_in[5];
    float* out = (float*)d_out;

    // 1) input projection GEMM -> g_xp
    dim3 g1((BATCH * T_STEPS) / BM, HID / BN);
    gemm_xp_kernel<<<g1, 256>>>(x, Wih, bh);

    // 2) persistent batch-parallel recurrence
    cudaFuncSetAttribute(rnn_recurrence_kernel,
                         cudaFuncAttributeMaxDynamicSharedMemorySize, 225280);
    rnn_recurrence_kernel<<<BATCH / 2, 256, 225280>>>(Whh);

    // 3) classifier head
    rnn_head_kernel<<<BATCH, 128>>>(fcw, fcb, out);
}